// round 1
// baseline (speedup 1.0000x reference)
#include <cuda_runtime.h>

#define N_TOK 8192
#define HID   8192
#define NG    16
#define NE    16

#define BM    64
#define BK    64
#define KSPL  16
#define NSTAGE (HID / BK)

typedef unsigned long long ull;

// ---------------- device scratch (no allocations allowed) ----------------
__device__ float d_gsum[NG];
__device__ float d_msum[NE];
__device__ int   d_gsel[N_TOK];
__device__ int   d_gcount[NG];
__device__ int   d_goff[NG];
__device__ int   d_gcur[NG];
__device__ int   d_perm[N_TOK];

// ---------------- f32x2 helpers (Blackwell packed fp32) ----------------
__device__ __forceinline__ ull ffma2(ull a, ull b, ull c) {
    ull d;
    asm("fma.rn.f32x2 %0, %1, %2, %3;" : "=l"(d) : "l"(a), "l"(b), "l"(c));
    return d;
}
__device__ __forceinline__ float2 unpk(ull v) {
    float lo, hi;
    asm("mov.b64 {%0,%1}, %2;" : "=f"(lo), "=f"(hi) : "l"(v));
    return make_float2(lo, hi);
}

struct __align__(16) SmemT {
    float  xs[BK][BM + 4];   // transposed X tile, padded (stride 68 floats, 16B-aligned rows)
    float2 w2[BK][NG];       // duplicated weights: w2[k][g] = (w, w)
};

// ============================================================
// Kernel 1: group-gate GEMM  C[64,16] = X_tile @ W1^T  + fused
//           softmax / argmax / group-prob sums / group histogram
// ============================================================
__global__ void __launch_bounds__(256, 1)
k_group_gemm(const float* __restrict__ X, const float* __restrict__ W1)
{
    __shared__ SmemT sm;
    __shared__ int shist[NG];

    const int tid  = threadIdx.x;
    const int blk  = blockIdx.x;
    const int tcol = tid & 7;            // 8 token-columns (8 tokens each)
    const int grow = (tid >> 3) & 1;     // 2 group-rows (8 groups each)
    const int ksl  = tid >> 4;           // 16 k-slices
    const int lt   = tid & 63;           // loader: token
    const int lq   = tid >> 6;           // loader: k-quad group (0..3)

    if (tid < NG) shist[tid] = 0;

    const float* xrow = X + (size_t)(blk * BM + lt) * HID + lq * 16;
    const int    wg   = tid & 15, wq = tid >> 4;
    const float* wrow = W1 + (size_t)wg * HID + wq * 4;

    ull acc[4][8];
#pragma unroll
    for (int a = 0; a < 4; a++)
#pragma unroll
        for (int b = 0; b < 8; b++) acc[a][b] = 0ULL;

    float4 xr[4];
    float4 wr;
#pragma unroll
    for (int j = 0; j < 4; j++) xr[j] = *reinterpret_cast<const float4*>(xrow + j * 4);
    wr = *reinterpret_cast<const float4*>(wrow);

    for (int s = 0; s < NSTAGE; s++) {
        __syncthreads();
        // stage stores (X transposed; W duplicated to float2)
#pragma unroll
        for (int j = 0; j < 4; j++) {
            const int k = lq * 16 + j * 4;
            sm.xs[k + 0][lt] = xr[j].x;
            sm.xs[k + 1][lt] = xr[j].y;
            sm.xs[k + 2][lt] = xr[j].z;
            sm.xs[k + 3][lt] = xr[j].w;
        }
        {
            const int k = wq * 4;
            sm.w2[k + 0][wg] = make_float2(wr.x, wr.x);
            sm.w2[k + 1][wg] = make_float2(wr.y, wr.y);
            sm.w2[k + 2][wg] = make_float2(wr.z, wr.z);
            sm.w2[k + 3][wg] = make_float2(wr.w, wr.w);
        }
        __syncthreads();
        // prefetch next stage into registers (overlaps with compute below)
        if (s + 1 < NSTAGE) {
            const float* xn = xrow + (size_t)(s + 1) * BK;
#pragma unroll
            for (int j = 0; j < 4; j++) xr[j] = *reinterpret_cast<const float4*>(xn + j * 4);
            wr = *reinterpret_cast<const float4*>(wrow + (size_t)(s + 1) * BK);
        }
        // compute: 4 k-steps per thread, 32 FFMA2 each
#pragma unroll
        for (int j = 0; j < 4; j++) {
            const int k = ksl * 4 + j;
            ulonglong2 xa = *reinterpret_cast<const ulonglong2*>(&sm.xs[k][tcol * 8]);
            ulonglong2 xb = *reinterpret_cast<const ulonglong2*>(&sm.xs[k][tcol * 8 + 4]);
            ulonglong2 wa = *reinterpret_cast<const ulonglong2*>(&sm.w2[k][grow * 8]);
            ulonglong2 wb = *reinterpret_cast<const ulonglong2*>(&sm.w2[k][grow * 8 + 2]);
            ulonglong2 wc = *reinterpret_cast<const ulonglong2*>(&sm.w2[k][grow * 8 + 4]);
            ulonglong2 wd = *reinterpret_cast<const ulonglong2*>(&sm.w2[k][grow * 8 + 6]);
            ull xv[4] = {xa.x, xa.y, xb.x, xb.y};
            ull wv[8] = {wa.x, wa.y, wb.x, wb.y, wc.x, wc.y, wd.x, wd.y};
#pragma unroll
            for (int t = 0; t < 4; t++)
#pragma unroll
                for (int g = 0; g < 8; g++)
                    acc[t][g] = ffma2(xv[t], wv[g], acc[t][g]);
        }
    }

    // ---- reduce across 16 k-slices into red[64][17] (aliases xs) ----
    __syncthreads();
    float* red = &sm.xs[0][0];
    for (int s = 0; s < KSPL; s++) {
        if (ksl == s) {
#pragma unroll
            for (int t = 0; t < 4; t++)
#pragma unroll
                for (int g = 0; g < 8; g++) {
                    float2 v = unpk(acc[t][g]);
                    const int t0 = tcol * 8 + 2 * t, gg = grow * 8 + g;
                    if (s == 0) {
                        red[t0 * 17 + gg] = v.x;
                        red[(t0 + 1) * 17 + gg] = v.y;
                    } else {
                        red[t0 * 17 + gg] += v.x;
                        red[(t0 + 1) * 17 + gg] += v.y;
                    }
                }
        }
        __syncthreads();
    }

    // ---- fused epilogue: softmax, argmax, prob sums, histogram ----
    float* pb = reinterpret_cast<float*>(&sm.w2[0][0]);  // [64][17]
    if (tid < BM) {
        float l[NG];
#pragma unroll
        for (int g = 0; g < NG; g++) l[g] = red[tid * 17 + g];
        float m = l[0];
        int   gi = 0;
#pragma unroll
        for (int g = 1; g < NG; g++)
            if (l[g] > m) { m = l[g]; gi = g; }
        float p[NG], ssum = 0.f;
#pragma unroll
        for (int g = 0; g < NG; g++) { p[g] = __expf(l[g] - m); ssum += p[g]; }
        const float inv = 1.0f / ssum;
#pragma unroll
        for (int g = 0; g < NG; g++) pb[tid * 17 + g] = p[g] * inv;
        const int n = blk * BM + tid;
        d_gsel[n] = gi;
        atomicAdd(&shist[gi], 1);
    }
    __syncthreads();
    if (tid < NG) {
        float s = 0.f;
        for (int t = 0; t < BM; t++) s += pb[t * 17 + tid];
        atomicAdd(&d_gsum[tid], s);
        atomicAdd(&d_gcount[tid], shist[tid]);
    }
}

// ============================================================
// Sorting pipeline: prefix + per-CTA aggregated scatter
// ============================================================
__global__ void k_zero()
{
    const int t = threadIdx.x;
    if (t < NG) { d_gsum[t] = 0.f; d_msum[t] = 0.f; d_gcount[t] = 0; }
}

__global__ void k_prefix()
{
    if (threadIdx.x == 0) {
        int a = 0;
        for (int g = 0; g < NG; g++) { d_goff[g] = a; d_gcur[g] = a; a += d_gcount[g]; }
    }
}

__global__ void k_scatter()
{
    __shared__ int cnt[NG], base[NG];
    const int tid = threadIdx.x;
    if (tid < NG) cnt[tid] = 0;
    __syncthreads();
    const int n = blockIdx.x * blockDim.x + tid;
    const int g = d_gsel[n];
    const int r = atomicAdd(&cnt[g], 1);
    __syncthreads();
    if (tid < NG) base[tid] = atomicAdd(&d_gcur[tid], cnt[tid]);
    __syncthreads();
    d_perm[base[g] + r] = n;
}

// ============================================================
// Kernel 2: mini-gate GEMM per (group, token-tile) with gathered rows,
//           fused softmax / top-4 / output write / mini-prob sums
// ============================================================
__global__ void __launch_bounds__(256, 1)
k_mini_gemm(const float* __restrict__ X, const float* __restrict__ WM,
            float* __restrict__ out)
{
    __shared__ SmemT sm;
    __shared__ int rows_s[BM];

    const int g     = blockIdx.y;
    const int cnt   = d_gcount[g];
    const int start = blockIdx.x * BM;
    if (start >= cnt) return;
    const int nvalid = min(BM, cnt - start);
    const int off    = d_goff[g];
    const int tid    = threadIdx.x;

    if (tid < BM) {
        int idx = start + tid;
        if (idx > cnt - 1) idx = cnt - 1;  // clamp: duplicate work, discarded
        rows_s[tid] = d_perm[off + idx];
    }
    __syncthreads();

    const int tcol = tid & 7, grow = (tid >> 3) & 1, ksl = tid >> 4;
    const int lt = tid & 63, lq = tid >> 6;
    const float* xrow  = X + (size_t)rows_s[lt] * HID + lq * 16;
    const float* wbase = WM + (size_t)g * HID * NE;   // layout [H][16], e contiguous

    ull acc[4][8];
#pragma unroll
    for (int a = 0; a < 4; a++)
#pragma unroll
        for (int b = 0; b < 8; b++) acc[a][b] = 0ULL;

    float4 xr[4];
    float4 wr;
#pragma unroll
    for (int j = 0; j < 4; j++) xr[j] = *reinterpret_cast<const float4*>(xrow + j * 4);
    wr = *reinterpret_cast<const float4*>(wbase + tid * 4);

    for (int s = 0; s < NSTAGE; s++) {
        __syncthreads();
#pragma unroll
        for (int j = 0; j < 4; j++) {
            const int k = lq * 16 + j * 4;
            sm.xs[k + 0][lt] = xr[j].x;
            sm.xs[k + 1][lt] = xr[j].y;
            sm.xs[k + 2][lt] = xr[j].z;
            sm.xs[k + 3][lt] = xr[j].w;
        }
        {
            const int k = tid >> 2, e0 = (tid & 3) * 4;  // float4 covers e0..e0+3 at fixed k
            sm.w2[k][e0 + 0] = make_float2(wr.x, wr.x);
            sm.w2[k][e0 + 1] = make_float2(wr.y, wr.y);
            sm.w2[k][e0 + 2] = make_float2(wr.z, wr.z);
            sm.w2[k][e0 + 3] = make_float2(wr.w, wr.w);
        }
        __syncthreads();
        if (s + 1 < NSTAGE) {
            const float* xn = xrow + (size_t)(s + 1) * BK;
#pragma unroll
            for (int j = 0; j < 4; j++) xr[j] = *reinterpret_cast<const float4*>(xn + j * 4);
            wr = *reinterpret_cast<const float4*>(wbase + (size_t)(s + 1) * BK * NE + tid * 4);
        }
#pragma unroll
        for (int j = 0; j < 4; j++) {
            const int k = ksl * 4 + j;
            ulonglong2 xa = *reinterpret_cast<const ulonglong2*>(&sm.xs[k][tcol * 8]);
            ulonglong2 xb = *reinterpret_cast<const ulonglong2*>(&sm.xs[k][tcol * 8 + 4]);
            ulonglong2 wa = *reinterpret_cast<const ulonglong2*>(&sm.w2[k][grow * 8]);
            ulonglong2 wb = *reinterpret_cast<const ulonglong2*>(&sm.w2[k][grow * 8 + 2]);
            ulonglong2 wc = *reinterpret_cast<const ulonglong2*>(&sm.w2[k][grow * 8 + 4]);
            ulonglong2 wd = *reinterpret_cast<const ulonglong2*>(&sm.w2[k][grow * 8 + 6]);
            ull xv[4] = {xa.x, xa.y, xb.x, xb.y};
            ull wv[8] = {wa.x, wa.y, wb.x, wb.y, wc.x, wc.y, wd.x, wd.y};
#pragma unroll
            for (int t = 0; t < 4; t++)
#pragma unroll
                for (int e = 0; e < 8; e++)
                    acc[t][e] = ffma2(xv[t], wv[e], acc[t][e]);
        }
    }

    __syncthreads();
    float* red = &sm.xs[0][0];
    for (int s = 0; s < KSPL; s++) {
        if (ksl == s) {
#pragma unroll
            for (int t = 0; t < 4; t++)
#pragma unroll
                for (int e = 0; e < 8; e++) {
                    float2 v = unpk(acc[t][e]);
                    const int t0 = tcol * 8 + 2 * t, ee = grow * 8 + e;
                    if (s == 0) {
                        red[t0 * 17 + ee] = v.x;
                        red[(t0 + 1) * 17 + ee] = v.y;
                    } else {
                        red[t0 * 17 + ee] += v.x;
                        red[(t0 + 1) * 17 + ee] += v.y;
                    }
                }
        }
        __syncthreads();
    }

    float* pb = reinterpret_cast<float*>(&sm.w2[0][0]);  // [64][17]
    if (tid < BM) {
        const bool valid = (tid < nvalid);
        float l[NE];
#pragma unroll
        for (int e = 0; e < NE; e++) l[e] = red[tid * 17 + e];
        float m = l[0];
#pragma unroll
        for (int e = 1; e < NE; e++) m = fmaxf(m, l[e]);
        float ex[NE], ssum = 0.f;
#pragma unroll
        for (int e = 0; e < NE; e++) { ex[e] = __expf(l[e] - m); ssum += ex[e]; }
        const float inv = 1.0f / ssum;
#pragma unroll
        for (int e = 0; e < NE; e++) pb[tid * 17 + e] = valid ? ex[e] * inv : 0.f;

        if (valid) {
            // top-4 by logit (== top-4 by prob); strict > keeps lowest index on tie,
            // matching jax top_k; emitted in descending order.
            float cur[NE];
#pragma unroll
            for (int e = 0; e < NE; e++) cur[e] = l[e];
            int   eidx[4];
            float ev[4];
            float den = 0.f;
#pragma unroll
            for (int j = 0; j < 4; j++) {
                float best = -3.4e38f;
                int   bi   = 0;
#pragma unroll
                for (int e = 0; e < NE; e++)
                    if (cur[e] > best) { best = cur[e]; bi = e; }
                cur[bi] = -3.4e38f;
                eidx[j] = bi;
                ev[j]   = ex[bi];
                den += ex[bi];
            }
            // top_group_prob cancels in normalization: final = ex_j / sum(top4 ex)
            const float invd = 1.0f / den;
            const int   n    = rows_s[tid];
#pragma unroll
            for (int j = 0; j < 4; j++) {
                out[(size_t)n * 4 + j] = ev[j] * invd;
                out[(size_t)N_TOK * 4 + (size_t)n * 4 + j] = (float)(g * NE + eidx[j]);
            }
        }
    }
    __syncthreads();
    if (tid < NE) {
        float s = 0.f;
        for (int t = 0; t < BM; t++) s += pb[t * 17 + tid];
        atomicAdd(&d_msum[tid], s);
    }
}

// ============================================================
// Finalize: aux loss = sum((gsum/N)^2) + sum((msum/N)^2)
// ============================================================
__global__ void k_final(float* __restrict__ out, int out_size)
{
    if (threadIdx.x == 0) {
        float a = 0.f;
        for (int i = 0; i < NG; i++) { float x = d_gsum[i] / (float)N_TOK; a += x * x; }
        for (int i = 0; i < NE; i++) { float x = d_msum[i] / (float)N_TOK; a += x * x; }
        out[out_size - 1] = a;
    }
}

// ============================================================
extern "C" void kernel_launch(void* const* d_in, const int* in_sizes, int n_in,
                              void* d_out, int out_size)
{
    const float* X  = (const float*)d_in[0];  // hidden_states [N, H]
    const float* W1 = (const float*)d_in[1];  // group_gate_w  [16, H]
    const float* WM = (const float*)d_in[2];  // mini_gates    [16, H, 16]
    float* out = (float*)d_out;               // [probs N*4 | indices N*4 | aux 1]

    k_zero<<<1, 32>>>();
    k_group_gemm<<<N_TOK / BM, 256>>>(X, W1);
    k_prefix<<<1, 32>>>();
    k_scatter<<<N_TOK / 256, 256>>>();
    k_mini_gemm<<<dim3(N_TOK / BM, NG), 256>>>(X, WM, out);
    k_final<<<1, 32>>>(out, out_size);
}

// round 2
// speedup vs baseline: 2.1705x; 2.1705x over previous
#include <cuda_runtime.h>
#include <cstdint>

#define N_TOK 8192
#define HID   8192
#define NG    16
#define NE    16

#define BM      32
#define BK      64
#define NSTAGE  (HID / BK)      // 128
#define NBUF    3

#define XS_STRIDE_B 272         // 68 floats per token row (16B aligned, bank-spread)
#define WS_STRIDE_B 80          // 20 floats per k row (16B aligned, bank-spread)
#define XS_BYTES (BM * XS_STRIDE_B)          // 8704
#define WS_BYTES (BK * WS_STRIDE_B)          // 5120
#define STAGE_BYTES (XS_BYTES + WS_BYTES)    // 13824
#define RING_BYTES  (NBUF * STAGE_BYTES)     // 41472 (< 48KB static smem)

typedef unsigned long long ull;

// ---------------- device scratch (no runtime allocation) ----------------
__device__ float d_w1t[HID * NG];   // W1 transposed: [k][g]
__device__ float d_gsum[NG];
__device__ float d_msum[NE];
__device__ int   d_gsel[N_TOK];
__device__ int   d_gcount[NG];
__device__ int   d_goff[NG];
__device__ int   d_gcur[NG];
__device__ int   d_perm[N_TOK];

// ---------------- helpers ----------------
__device__ __forceinline__ ull ffma2(ull a, ull b, ull c) {
    ull d;
    asm("fma.rn.f32x2 %0, %1, %2, %3;" : "=l"(d) : "l"(a), "l"(b), "l"(c));
    return d;
}
__device__ __forceinline__ ull dup2(float x) {
    ull d;
    asm("mov.b64 %0, {%1, %1};" : "=l"(d) : "f"(x));
    return d;
}
__device__ __forceinline__ float2 unpk(ull v) {
    float2 r;
    asm("mov.b64 {%0, %1}, %2;" : "=f"(r.x), "=f"(r.y) : "l"(v));
    return r;
}
__device__ __forceinline__ uint32_t s2u(const void* p) {
    return (uint32_t)__cvta_generic_to_shared(p);
}
__device__ __forceinline__ void cp16(uint32_t dst, const void* src) {
    asm volatile("cp.async.cg.shared.global [%0], [%1], 16;" :: "r"(dst), "l"(src));
}
#define CP_COMMIT() asm volatile("cp.async.commit_group;")
#define CP_WAIT1()  asm volatile("cp.async.wait_group 1;")

// ============================================================
// Prep: transpose W1 -> d_w1t[k][g]; zero accumulators
// ============================================================
__global__ void k_prep(const float* __restrict__ W1)
{
    const int k = blockIdx.x * 256 + threadIdx.x;   // 32 blocks x 256 = 8192
    float v[NG];
#pragma unroll
    for (int g = 0; g < NG; g++) v[g] = W1[(size_t)g * HID + k];
#pragma unroll
    for (int q = 0; q < 4; q++)
        *reinterpret_cast<float4*>(d_w1t + (size_t)k * NG + q * 4) =
            make_float4(v[q * 4], v[q * 4 + 1], v[q * 4 + 2], v[q * 4 + 3]);
    if (blockIdx.x == 0 && threadIdx.x < NG) {
        d_gsum[threadIdx.x] = 0.f;
        d_msum[threadIdx.x] = 0.f;
        d_gcount[threadIdx.x] = 0;
    }
}

// ============================================================
// Kernel 1: group-gate GEMM (32 tok x 16 grp per CTA) + epilogue
// ============================================================
__global__ void __launch_bounds__(256, 2)
k_group_gemm(const float* __restrict__ X)
{
    __shared__ __align__(16) char smbuf[RING_BYTES];
    __shared__ int shist[NG];

    const int tid = threadIdx.x, blk = blockIdx.x;
    const int tcol = tid & 7, grow = (tid >> 3) & 1, ksl = tid >> 4;
    if (tid < NG) shist[tid] = 0;

    // ---- loader mapping: X (2 chunks/thread), W (1 chunk/thread) ----
    const int lr = tid >> 4, lc = tid & 15;   // row 0..15 (+16), chunk 0..15
    const char* xs0 = (const char*)(X + (size_t)(blk * BM + lr) * HID) + lc * 16;
    const char* xs1 = (const char*)(X + (size_t)(blk * BM + lr + 16) * HID) + lc * 16;
    const int wk = tid >> 2, wc = tid & 3;
    const char* wsr = (const char*)d_w1t + wk * 64 + wc * 16;

    const uint32_t smb = s2u(smbuf);
    const uint32_t xd0 = smb + lr * XS_STRIDE_B + lc * 16;
    const uint32_t xd1 = xd0 + 16 * XS_STRIDE_B;
    const uint32_t wd  = smb + XS_BYTES + wk * WS_STRIDE_B + wc * 16;

#define ISSUE(s) do { uint32_t _b = ((s) % NBUF) * STAGE_BYTES;        \
        cp16(xd0 + _b, xs0 + (size_t)(s) * 256);                       \
        cp16(xd1 + _b, xs1 + (size_t)(s) * 256);                       \
        cp16(wd  + _b, wsr + (size_t)(s) * 4096); } while (0)

    ISSUE(0); CP_COMMIT();
    ISSUE(1); CP_COMMIT();

    ull acc[4][4];
#pragma unroll
    for (int i = 0; i < 4; i++)
#pragma unroll
        for (int p = 0; p < 4; p++) acc[i][p] = 0ULL;

    for (int s = 0; s < NSTAGE; s++) {
        CP_WAIT1();
        __syncthreads();
        if (s + 2 < NSTAGE) ISSUE(s + 2);
        CP_COMMIT();

        const char* bb = smbuf + (s % NBUF) * STAGE_BYTES;
        float4 xv[4];
#pragma unroll
        for (int i = 0; i < 4; i++)
            xv[i] = *(const float4*)(bb + (tcol + 8 * i) * XS_STRIDE_B + ksl * 16);
#pragma unroll
        for (int j = 0; j < 4; j++) {
            const char* wb = bb + XS_BYTES + (ksl * 4 + j) * WS_STRIDE_B + grow * 32;
            ulonglong2 wlo = *(const ulonglong2*)wb;
            ulonglong2 whi = *(const ulonglong2*)(wb + 16);
            ull w[4] = {wlo.x, wlo.y, whi.x, whi.y};
#pragma unroll
            for (int i = 0; i < 4; i++) {
                ull xd = dup2(reinterpret_cast<const float*>(&xv[i])[j]);
#pragma unroll
                for (int p = 0; p < 4; p++) acc[i][p] = ffma2(xd, w[p], acc[i][p]);
            }
        }
    }

    // ---- cross-ksl reduction into red[32][17] ----
    __syncthreads();
    float* red = reinterpret_cast<float*>(smbuf);
    for (int q = 0; q < 16; q++) {
        if (ksl == q) {
#pragma unroll
            for (int i = 0; i < 4; i++)
#pragma unroll
                for (int p = 0; p < 4; p++) {
                    float2 v = unpk(acc[i][p]);
                    const int t = tcol + 8 * i, g = grow * 8 + 2 * p;
                    if (q == 0) { red[t * 17 + g] = v.x; red[t * 17 + g + 1] = v.y; }
                    else        { red[t * 17 + g] += v.x; red[t * 17 + g + 1] += v.y; }
                }
        }
        __syncthreads();
    }

    // ---- epilogue: softmax / argmax / sums / histogram ----
    float* pb = reinterpret_cast<float*>(smbuf + 2560);   // [32][17]
    if (tid < BM) {
        float l[NG];
#pragma unroll
        for (int g = 0; g < NG; g++) l[g] = red[tid * 17 + g];
        float m = l[0];
        int   gi = 0;
#pragma unroll
        for (int g = 1; g < NG; g++)
            if (l[g] > m) { m = l[g]; gi = g; }
        float p[NG], ssum = 0.f;
#pragma unroll
        for (int g = 0; g < NG; g++) { p[g] = __expf(l[g] - m); ssum += p[g]; }
        const float inv = 1.0f / ssum;
#pragma unroll
        for (int g = 0; g < NG; g++) pb[tid * 17 + g] = p[g] * inv;
        d_gsel[blk * BM + tid] = gi;
        atomicAdd(&shist[gi], 1);
    }
    __syncthreads();
    if (tid < NG) {
        float ssum = 0.f;
        for (int t = 0; t < BM; t++) ssum += pb[t * 17 + tid];
        atomicAdd(&d_gsum[tid], ssum);
        atomicAdd(&d_gcount[tid], shist[tid]);
    }
#undef ISSUE
}

// ============================================================
// Sorting pipeline
// ============================================================
__global__ void k_prefix()
{
    if (threadIdx.x == 0) {
        int a = 0;
        for (int g = 0; g < NG; g++) { d_goff[g] = a; d_gcur[g] = a; a += d_gcount[g]; }
    }
}

__global__ void k_scatter()
{
    __shared__ int cnt[NG], base[NG];
    const int tid = threadIdx.x;
    if (tid < NG) cnt[tid] = 0;
    __syncthreads();
    const int n = blockIdx.x * blockDim.x + tid;
    const int g = d_gsel[n];
    const int r = atomicAdd(&cnt[g], 1);
    __syncthreads();
    if (tid < NG) base[tid] = atomicAdd(&d_gcur[tid], cnt[tid]);
    __syncthreads();
    d_perm[base[g] + r] = n;
}

// ============================================================
// Kernel 2: mini-gate GEMM (gathered rows) + top-4 epilogue
// ============================================================
__global__ void __launch_bounds__(256, 2)
k_mini_gemm(const float* __restrict__ X, const float* __restrict__ WM,
            float* __restrict__ out)
{
    const int g     = blockIdx.y;
    const int cnt   = d_gcount[g];
    const int start = blockIdx.x * BM;
    if (start >= cnt) return;
    const int nvalid = min(BM, cnt - start);
    const int off    = d_goff[g];
    const int tid    = threadIdx.x;

    __shared__ __align__(16) char smbuf[RING_BYTES];
    __shared__ int rows_s[BM];

    if (tid < BM) {
        int idx = start + tid;
        if (idx > cnt - 1) idx = cnt - 1;   // clamp: duplicate rows, results discarded
        rows_s[tid] = d_perm[off + idx];
    }
    __syncthreads();

    const int tcol = tid & 7, grow = (tid >> 3) & 1, ksl = tid >> 4;
    const int lr = tid >> 4, lc = tid & 15;
    const char* xs0 = (const char*)(X + (size_t)rows_s[lr] * HID) + lc * 16;
    const char* xs1 = (const char*)(X + (size_t)rows_s[lr + 16] * HID) + lc * 16;
    const int wk = tid >> 2, wc = tid & 3;
    const char* wsr = (const char*)(WM + (size_t)g * HID * NE) + wk * 64 + wc * 16;

    const uint32_t smb = s2u(smbuf);
    const uint32_t xd0 = smb + lr * XS_STRIDE_B + lc * 16;
    const uint32_t xd1 = xd0 + 16 * XS_STRIDE_B;
    const uint32_t wd  = smb + XS_BYTES + wk * WS_STRIDE_B + wc * 16;

#define ISSUE(s) do { uint32_t _b = ((s) % NBUF) * STAGE_BYTES;        \
        cp16(xd0 + _b, xs0 + (size_t)(s) * 256);                       \
        cp16(xd1 + _b, xs1 + (size_t)(s) * 256);                       \
        cp16(wd  + _b, wsr + (size_t)(s) * 4096); } while (0)

    ISSUE(0); CP_COMMIT();
    ISSUE(1); CP_COMMIT();

    ull acc[4][4];
#pragma unroll
    for (int i = 0; i < 4; i++)
#pragma unroll
        for (int p = 0; p < 4; p++) acc[i][p] = 0ULL;

    for (int s = 0; s < NSTAGE; s++) {
        CP_WAIT1();
        __syncthreads();
        if (s + 2 < NSTAGE) ISSUE(s + 2);
        CP_COMMIT();

        const char* bb = smbuf + (s % NBUF) * STAGE_BYTES;
        float4 xv[4];
#pragma unroll
        for (int i = 0; i < 4; i++)
            xv[i] = *(const float4*)(bb + (tcol + 8 * i) * XS_STRIDE_B + ksl * 16);
#pragma unroll
        for (int j = 0; j < 4; j++) {
            const char* wb = bb + XS_BYTES + (ksl * 4 + j) * WS_STRIDE_B + grow * 32;
            ulonglong2 wlo = *(const ulonglong2*)wb;
            ulonglong2 whi = *(const ulonglong2*)(wb + 16);
            ull w[4] = {wlo.x, wlo.y, whi.x, whi.y};
#pragma unroll
            for (int i = 0; i < 4; i++) {
                ull xd = dup2(reinterpret_cast<const float*>(&xv[i])[j]);
#pragma unroll
                for (int p = 0; p < 4; p++) acc[i][p] = ffma2(xd, w[p], acc[i][p]);
            }
        }
    }

    __syncthreads();
    float* red = reinterpret_cast<float*>(smbuf);
    for (int q = 0; q < 16; q++) {
        if (ksl == q) {
#pragma unroll
            for (int i = 0; i < 4; i++)
#pragma unroll
                for (int p = 0; p < 4; p++) {
                    float2 v = unpk(acc[i][p]);
                    const int t = tcol + 8 * i, e = grow * 8 + 2 * p;
                    if (q == 0) { red[t * 17 + e] = v.x; red[t * 17 + e + 1] = v.y; }
                    else        { red[t * 17 + e] += v.x; red[t * 17 + e + 1] += v.y; }
                }
        }
        __syncthreads();
    }

    float* pb = reinterpret_cast<float*>(smbuf + 2560);   // [32][17]
    if (tid < BM) {
        const bool valid = (tid < nvalid);
        float l[NE];
#pragma unroll
        for (int e = 0; e < NE; e++) l[e] = red[tid * 17 + e];
        float m = l[0];
#pragma unroll
        for (int e = 1; e < NE; e++) m = fmaxf(m, l[e]);
        float ex[NE], ssum = 0.f;
#pragma unroll
        for (int e = 0; e < NE; e++) { ex[e] = __expf(l[e] - m); ssum += ex[e]; }
        const float inv = 1.0f / ssum;
#pragma unroll
        for (int e = 0; e < NE; e++) pb[tid * 17 + e] = valid ? ex[e] * inv : 0.f;

        if (valid) {
            // top-4 by logit; strict > keeps lowest index on ties (matches lax.top_k)
            float cur[NE];
#pragma unroll
            for (int e = 0; e < NE; e++) cur[e] = l[e];
            int   eidx[4];
            float ev[4];
            float den = 0.f;
#pragma unroll
            for (int j = 0; j < 4; j++) {
                float best = -3.4e38f;
                int   bi   = 0;
#pragma unroll
                for (int e = 0; e < NE; e++)
                    if (cur[e] > best) { best = cur[e]; bi = e; }
                cur[bi] = -3.4e38f;
                eidx[j] = bi;
                ev[j]   = ex[bi];
                den += ex[bi];
            }
            // group prob cancels in normalization: final = ex_j / sum(top4 ex)
            const float invd = 1.0f / den;
            const int   n    = rows_s[tid];
#pragma unroll
            for (int j = 0; j < 4; j++) {
                out[(size_t)n * 4 + j] = ev[j] * invd;
                out[(size_t)N_TOK * 4 + (size_t)n * 4 + j] = (float)(g * NE + eidx[j]);
            }
        }
    }
    __syncthreads();
    if (tid < NE) {
        float ssum = 0.f;
        for (int t = 0; t < BM; t++) ssum += pb[t * 17 + tid];
        atomicAdd(&d_msum[tid], ssum);
    }
#undef ISSUE
}

// ============================================================
// Finalize: aux loss
// ============================================================
__global__ void k_final(float* __restrict__ out, int out_size)
{
    if (threadIdx.x == 0) {
        float a = 0.f;
        for (int i = 0; i < NG; i++) { float x = d_gsum[i] / (float)N_TOK; a += x * x; }
        for (int i = 0; i < NE; i++) { float x = d_msum[i] / (float)N_TOK; a += x * x; }
        out[out_size - 1] = a;
    }
}

// ============================================================
extern "C" void kernel_launch(void* const* d_in, const int* in_sizes, int n_in,
                              void* d_out, int out_size)
{
    const float* X  = (const float*)d_in[0];  // hidden_states [N, H]
    const float* W1 = (const float*)d_in[1];  // group_gate_w  [16, H]
    const float* WM = (const float*)d_in[2];  // mini_gates    [16, H, 16]
    float* out = (float*)d_out;               // [probs N*4 | indices N*4 | aux]

    k_prep<<<HID / 256, 256>>>(W1);
    k_group_gemm<<<N_TOK / BM, 256>>>(X);
    k_prefix<<<1, 32>>>();
    k_scatter<<<N_TOK / 256, 256>>>();
    k_mini_gemm<<<dim3(N_TOK / BM, NG), 256>>>(X, WM, out);
    k_final<<<1, 32>>>(out, out_size);
}